// round 1
// baseline (speedup 1.0000x reference)
#include <cuda_runtime.h>

// Problem dims (fixed for this problem instance)
#define T_DIM 100
#define B_DIM 128
#define F_DIM 4096
#define C_DIM 10

#define ROWS_PER_BLOCK 4          // consecutive (t,b) rows per block
#define THREADS_K1 128
#define F4_DIM (F_DIM / 4)        // 1024 float4 per row
#define ITERS (F4_DIM / THREADS_K1)  // 8

// Scratch for current[t,b,c] (512 KB) — __device__ global, no allocation.
__device__ float g_current[T_DIM * B_DIM * C_DIM];

// Kernel 1: current[t,b,c] = 2 * sum_f spike[t,b,f]*mask[t,b,f]*W[c,f] + bias[c]
// One block handles ROWS_PER_BLOCK consecutive flattened rows (row = t*B + b),
// which are contiguous in memory (stride F).
__global__ __launch_bounds__(THREADS_K1)
void snn_gemv_kernel(const float* __restrict__ spike,
                     const float* __restrict__ mask,
                     const float* __restrict__ W,
                     const float* __restrict__ bias)
{
    const int row0 = blockIdx.x * ROWS_PER_BLOCK;
    const int tid  = threadIdx.x;

    const float4* sp = reinterpret_cast<const float4*>(spike) + (size_t)row0 * F4_DIM;
    const float4* mk = reinterpret_cast<const float4*>(mask)  + (size_t)row0 * F4_DIM;
    const float4* W4 = reinterpret_cast<const float4*>(W);

    float acc[ROWS_PER_BLOCK][C_DIM];
#pragma unroll
    for (int r = 0; r < ROWS_PER_BLOCK; ++r)
#pragma unroll
        for (int c = 0; c < C_DIM; ++c)
            acc[r][c] = 0.0f;

#pragma unroll
    for (int it = 0; it < ITERS; ++it) {
        const int f4 = tid + it * THREADS_K1;

        // x = spike * mask  (0 or 1)
        float4 x[ROWS_PER_BLOCK];
#pragma unroll
        for (int r = 0; r < ROWS_PER_BLOCK; ++r) {
            const float4 s4 = sp[(size_t)r * F4_DIM + f4];
            const float4 m4 = mk[(size_t)r * F4_DIM + f4];
            x[r].x = s4.x * m4.x;
            x[r].y = s4.y * m4.y;
            x[r].z = s4.z * m4.z;
            x[r].w = s4.w * m4.w;
        }

        // 10 W loads amortized across 4 rows; W stays L1-resident per SM.
#pragma unroll
        for (int c = 0; c < C_DIM; ++c) {
            const float4 wv = W4[(size_t)c * F4_DIM + f4];
#pragma unroll
            for (int r = 0; r < ROWS_PER_BLOCK; ++r) {
                float a = acc[r][c];
                a = fmaf(x[r].x, wv.x, a);
                a = fmaf(x[r].y, wv.y, a);
                a = fmaf(x[r].z, wv.z, a);
                a = fmaf(x[r].w, wv.w, a);
                acc[r][c] = a;
            }
        }
    }

    // Reduce across the 128 threads: warp shuffle, then cross-warp via smem.
    __shared__ float sred[THREADS_K1 / 32][ROWS_PER_BLOCK * C_DIM];
    const int lane = tid & 31;
    const int warp = tid >> 5;

#pragma unroll
    for (int r = 0; r < ROWS_PER_BLOCK; ++r) {
#pragma unroll
        for (int c = 0; c < C_DIM; ++c) {
            float v = acc[r][c];
#pragma unroll
            for (int o = 16; o > 0; o >>= 1)
                v += __shfl_down_sync(0xffffffffu, v, o);
            if (lane == 0)
                sred[warp][r * C_DIM + c] = v;
        }
    }
    __syncthreads();

    if (tid < ROWS_PER_BLOCK * C_DIM) {
        float s = sred[0][tid] + sred[1][tid] + sred[2][tid] + sred[3][tid];
        const int r = tid / C_DIM;
        const int c = tid % C_DIM;
        // 2.0f = 1/keep (dropout scaling); bias added once here.
        g_current[(size_t)(row0 + r) * C_DIM + c] = 2.0f * s + bias[c];
    }
}

// Kernel 2: LIF scan over T for each (b,c) sequence.
// v = 0.9*v + cur; s = heaviside(v - 1); v -= s
__global__ __launch_bounds__(128)
void snn_scan_kernel(float* __restrict__ out)
{
    const int idx = blockIdx.x * blockDim.x + threadIdx.x;  // 0..1279
    if (idx >= B_DIM * C_DIM) return;

    float v = 0.0f;
#pragma unroll 4
    for (int t = 0; t < T_DIM; ++t) {
        const float cur = g_current[(size_t)t * (B_DIM * C_DIM) + idx];
        v = 0.9f * v + cur;
        const float s = (v - 1.0f) > 0.0f ? 1.0f : 0.0f;
        out[(size_t)t * (B_DIM * C_DIM) + idx] = s;
        v -= s;
    }
}

extern "C" void kernel_launch(void* const* d_in, const int* in_sizes, int n_in,
                              void* d_out, int out_size)
{
    const float* spike = (const float*)d_in[0];  // [T,B,F]
    const float* mask  = (const float*)d_in[1];  // [T,B,F]
    const float* W     = (const float*)d_in[2];  // [C,F]
    const float* bias  = (const float*)d_in[3];  // [C]
    float* out = (float*)d_out;                  // [T,B,C]

    const int n_rows = T_DIM * B_DIM;                    // 12800
    const int grid1  = n_rows / ROWS_PER_BLOCK;          // 3200

    snn_gemv_kernel<<<grid1, THREADS_K1>>>(spike, mask, W, bias);

    const int n_seq  = B_DIM * C_DIM;                    // 1280
    snn_scan_kernel<<<(n_seq + 127) / 128, 128>>>(out);
}

// round 2
// speedup vs baseline: 1.2224x; 1.2224x over previous
#include <cuda_runtime.h>

// Problem dims (fixed for this problem instance)
#define T_DIM 100
#define B_DIM 128
#define F_DIM 4096
#define C_DIM 10

#define ROWS_PER_BLOCK 8          // consecutive (t,b) rows per block (same t; 128 % 8 == 0)
#define THREADS_K1 128
#define F4_DIM (F_DIM / 4)        // 1024 float4 per row
#define ITERS (F4_DIM / THREADS_K1)  // 8
#define BC (B_DIM * C_DIM)        // 1280

// Scratch for current, TRANSPOSED: g_currentT[(b*C + c) * T + t]  (512 KB)
__device__ float g_currentT[BC * T_DIM];

// Kernel 1: current[t,b,c] = 2 * sum_f spike[t,b,f]*mask[t,b,f]*W[c,f] + bias[c]
// One block handles ROWS_PER_BLOCK consecutive flattened rows (row = t*B + b).
// spike/mask loaded with __ldcs (evict-first) so W stays L1-resident.
__global__ __launch_bounds__(THREADS_K1)
void snn_gemv_kernel(const float* __restrict__ spike,
                     const float* __restrict__ mask,
                     const float* __restrict__ W,
                     const float* __restrict__ bias)
{
    const int row0 = blockIdx.x * ROWS_PER_BLOCK;
    const int tid  = threadIdx.x;

    const float4* sp = reinterpret_cast<const float4*>(spike) + (size_t)row0 * F4_DIM;
    const float4* mk = reinterpret_cast<const float4*>(mask)  + (size_t)row0 * F4_DIM;
    const float4* W4 = reinterpret_cast<const float4*>(W);

    float acc[ROWS_PER_BLOCK][C_DIM];
#pragma unroll
    for (int r = 0; r < ROWS_PER_BLOCK; ++r)
#pragma unroll
        for (int c = 0; c < C_DIM; ++c)
            acc[r][c] = 0.0f;

#pragma unroll
    for (int it = 0; it < ITERS; ++it) {
        const int f4 = tid + it * THREADS_K1;

        // x = spike * mask (0 or 1); streaming loads, evict-first.
        float4 x[ROWS_PER_BLOCK];
#pragma unroll
        for (int r = 0; r < ROWS_PER_BLOCK; ++r) {
            const float4 s4 = __ldcs(&sp[(size_t)r * F4_DIM + f4]);
            const float4 m4 = __ldcs(&mk[(size_t)r * F4_DIM + f4]);
            x[r].x = s4.x * m4.x;
            x[r].y = s4.y * m4.y;
            x[r].z = s4.z * m4.z;
            x[r].w = s4.w * m4.w;
        }

        // 10 W loads amortized across 8 rows; W stays L1-resident.
#pragma unroll
        for (int c = 0; c < C_DIM; ++c) {
            const float4 wv = __ldg(&W4[(size_t)c * F4_DIM + f4]);
#pragma unroll
            for (int r = 0; r < ROWS_PER_BLOCK; ++r) {
                float a = acc[r][c];
                a = fmaf(x[r].x, wv.x, a);
                a = fmaf(x[r].y, wv.y, a);
                a = fmaf(x[r].z, wv.z, a);
                a = fmaf(x[r].w, wv.w, a);
                acc[r][c] = a;
            }
        }
    }

    // Reduce across the 128 threads: warp shuffle, then cross-warp via smem.
    __shared__ float sred[THREADS_K1 / 32][ROWS_PER_BLOCK * C_DIM];
    const int lane = tid & 31;
    const int warp = tid >> 5;

#pragma unroll
    for (int r = 0; r < ROWS_PER_BLOCK; ++r) {
#pragma unroll
        for (int c = 0; c < C_DIM; ++c) {
            float v = acc[r][c];
#pragma unroll
            for (int o = 16; o > 0; o >>= 1)
                v += __shfl_down_sync(0xffffffffu, v, o);
            if (lane == 0)
                sred[warp][r * C_DIM + c] = v;
        }
    }
    __syncthreads();

    if (tid < ROWS_PER_BLOCK * C_DIM) {
        float s = sred[0][tid] + sred[1][tid] + sred[2][tid] + sred[3][tid];
        const int r = tid / C_DIM;
        const int c = tid % C_DIM;
        const int row = row0 + r;
        const int t = row / B_DIM;
        const int b = row % B_DIM;
        // 2.0f = 1/keep (dropout scaling); bias added once here. Transposed store.
        g_currentT[(size_t)(b * C_DIM + c) * T_DIM + t] = 2.0f * s + bias[c];
    }
}

// Kernel 2: LIF scan over T for each (b,c) sequence.
// v = 0.9*v + cur; s = heaviside(v - 1); v -= s
// Reads its own contiguous 400B run via 25 independent float4 loads.
__global__ __launch_bounds__(128)
void snn_scan_kernel(float* __restrict__ out)
{
    const int idx = blockIdx.x * blockDim.x + threadIdx.x;  // 0..1279
    if (idx >= BC) return;

    const float4* cur4 = reinterpret_cast<const float4*>(g_currentT + (size_t)idx * T_DIM);

    float vals[T_DIM];
#pragma unroll
    for (int i = 0; i < T_DIM / 4; ++i) {
        const float4 c4 = cur4[i];
        vals[4 * i + 0] = c4.x;
        vals[4 * i + 1] = c4.y;
        vals[4 * i + 2] = c4.z;
        vals[4 * i + 3] = c4.w;
    }

    float v = 0.0f;
#pragma unroll
    for (int t = 0; t < T_DIM; ++t) {
        v = 0.9f * v + vals[t];
        const float s = (v - 1.0f) > 0.0f ? 1.0f : 0.0f;
        out[(size_t)t * BC + idx] = s;   // coalesced across threads
        v -= s;
    }
}

extern "C" void kernel_launch(void* const* d_in, const int* in_sizes, int n_in,
                              void* d_out, int out_size)
{
    const float* spike = (const float*)d_in[0];  // [T,B,F]
    const float* mask  = (const float*)d_in[1];  // [T,B,F]
    const float* W     = (const float*)d_in[2];  // [C,F]
    const float* bias  = (const float*)d_in[3];  // [C]
    float* out = (float*)d_out;                  // [T,B,C]

    const int n_rows = T_DIM * B_DIM;                    // 12800
    const int grid1  = n_rows / ROWS_PER_BLOCK;          // 1600

    snn_gemv_kernel<<<grid1, THREADS_K1>>>(spike, mask, W, bias);

    snn_scan_kernel<<<(BC + 127) / 128, 128>>>(out);
}